// round 1
// baseline (speedup 1.0000x reference)
#include <cuda_runtime.h>

// ---------------------------------------------------------------------------
// Problem constants
// ---------------------------------------------------------------------------
#define SNN_B   128
#define SNN_T   200
#define SNN_NI  4096
#define SNN_NH  1024
#define SNN_NO  2
#define SNN_M   (SNN_B * SNN_T)          // 25600 GEMM rows

// Scratch for cur1_all [B*T, NH] = 100 MB (static device array; no cudaMalloc)
static __device__ float g_cur1[(size_t)SNN_M * SNN_NH];

// ---------------------------------------------------------------------------
// Kernel 1: fc1 GEMM  C[m,n] = sum_k x[m,k] * w1[n,k] + b1[n]
// fp32, 128x128x16 SMEM-tiled, 256 threads, 8x8 per-thread microtile.
// ---------------------------------------------------------------------------
__global__ __launch_bounds__(256)
void fc1_gemm(const float* __restrict__ A,     // [M, K] = x flattened
              const float* __restrict__ W,     // [N, K] = w1
              const float* __restrict__ bias)  // [N]
{
    const int K = SNN_NI;
    __shared__ float As[16][128];
    __shared__ float Ws[16][128];

    const int tid  = threadIdx.x;
    const int bn   = blockIdx.x;          // 0..7
    const int bm   = blockIdx.y;          // 0..199
    const int lrow = tid >> 2;            // 0..63
    const int lc4  = (tid & 3) << 2;      // 0,4,8,12
    const int tx   = tid & 15;
    const int ty   = tid >> 4;

    const float* Ab = A + (size_t)bm * 128 * K;
    const float* Wb = W + (size_t)bn * 128 * K;

    float acc[8][8];
#pragma unroll
    for (int i = 0; i < 8; i++)
#pragma unroll
        for (int j = 0; j < 8; j++) acc[i][j] = 0.f;

    for (int k0 = 0; k0 < K; k0 += 16) {
        // Global loads for this k-tile (issued before the barrier so they
        // overlap the previous tile's compute on other warps).
        float4 a0 = *(const float4*)(Ab + (size_t)lrow        * K + k0 + lc4);
        float4 a1 = *(const float4*)(Ab + (size_t)(lrow + 64) * K + k0 + lc4);
        float4 w0 = *(const float4*)(Wb + (size_t)lrow        * K + k0 + lc4);
        float4 w1 = *(const float4*)(Wb + (size_t)(lrow + 64) * K + k0 + lc4);

        __syncthreads();   // previous tile's compute done reading SMEM
        As[lc4 + 0][lrow]      = a0.x;
        As[lc4 + 1][lrow]      = a0.y;
        As[lc4 + 2][lrow]      = a0.z;
        As[lc4 + 3][lrow]      = a0.w;
        As[lc4 + 0][lrow + 64] = a1.x;
        As[lc4 + 1][lrow + 64] = a1.y;
        As[lc4 + 2][lrow + 64] = a1.z;
        As[lc4 + 3][lrow + 64] = a1.w;
        Ws[lc4 + 0][lrow]      = w0.x;
        Ws[lc4 + 1][lrow]      = w0.y;
        Ws[lc4 + 2][lrow]      = w0.z;
        Ws[lc4 + 3][lrow]      = w0.w;
        Ws[lc4 + 0][lrow + 64] = w1.x;
        Ws[lc4 + 1][lrow + 64] = w1.y;
        Ws[lc4 + 2][lrow + 64] = w1.z;
        Ws[lc4 + 3][lrow + 64] = w1.w;
        __syncthreads();

#pragma unroll
        for (int kk = 0; kk < 16; kk++) {
            float ar[8], br[8];
            *(float4*)(ar)     = *(const float4*)&As[kk][ty * 8];
            *(float4*)(ar + 4) = *(const float4*)&As[kk][ty * 8 + 4];
            *(float4*)(br)     = *(const float4*)&Ws[kk][tx * 8];
            *(float4*)(br + 4) = *(const float4*)&Ws[kk][tx * 8 + 4];
#pragma unroll
            for (int i = 0; i < 8; i++)
#pragma unroll
                for (int j = 0; j < 8; j++)
                    acc[i][j] = fmaf(ar[i], br[j], acc[i][j]);
        }
    }

    const int n0 = bn * 128 + tx * 8;
    const int m0 = bm * 128 + ty * 8;
    float bv[8];
#pragma unroll
    for (int j = 0; j < 8; j++) bv[j] = bias[n0 + j];

#pragma unroll
    for (int i = 0; i < 8; i++) {
        float4 o0, o1;
        o0.x = acc[i][0] + bv[0];
        o0.y = acc[i][1] + bv[1];
        o0.z = acc[i][2] + bv[2];
        o0.w = acc[i][3] + bv[3];
        o1.x = acc[i][4] + bv[4];
        o1.y = acc[i][5] + bv[5];
        o1.z = acc[i][6] + bv[6];
        o1.w = acc[i][7] + bv[7];
        float* Crow = g_cur1 + (size_t)(m0 + i) * SNN_NH + n0;
        *(float4*)(Crow)     = o0;
        *(float4*)(Crow + 4) = o1;
    }
}

// ---------------------------------------------------------------------------
// Kernel 2: sequential SNN scan. One CTA per batch, thread h owns neuron h's
// (syn1, mem1) state in registers; fc2 is a 2-value block reduction/step.
// ---------------------------------------------------------------------------
__global__ __launch_bounds__(1024)
void snn_scan(const float* __restrict__ w2,   // [2, 1024]
              const float* __restrict__ b2,   // [2]
              float* __restrict__ out_mem,    // [B, T, 2]
              float* __restrict__ out_spk)    // [B, T, 2]
{
    const int b = blockIdx.x;
    const int h = threadIdx.x;
    const float ALPHA = 0.8187307530779818f;  // exp(-0.2)
    const float BETA  = 0.9048374180359595f;  // exp(-0.1)

    __shared__ float red0[32];
    __shared__ float red1[32];

    const float w20 = w2[h];
    const float w21 = w2[SNN_NH + h];
    const float b20 = b2[0];
    const float b21 = b2[1];

    float syn1 = 0.f, mem1 = 0.f;
    float syn2a = 0.f, mem2a = 0.f, syn2b = 0.f, mem2b = 0.f;

    const float* cp = g_cur1 + (size_t)b * SNN_T * SNN_NH + h;
    float cur_next = cp[0];

    const int lane = h & 31;
    const int warp = h >> 5;

    for (int t = 0; t < SNN_T; t++) {
        float cur = cur_next;
        if (t + 1 < SNN_T) cur_next = cp[(size_t)(t + 1) * SNN_NH];

        // layer-1 Synaptic neuron
        float r1 = (mem1 > 1.0f) ? 1.0f : 0.0f;       // reset from PREVIOUS mem
        syn1 = fmaf(ALPHA, syn1, cur);
        mem1 = fmaf(BETA, mem1, syn1) - r1;
        float spk = (mem1 > 1.0f) ? 1.0f : 0.0f;

        // fc2: reduce spk * w2 over 1024 neurons (two scalars)
        float v0 = spk * w20;
        float v1 = spk * w21;
#pragma unroll
        for (int off = 16; off > 0; off >>= 1) {
            v0 += __shfl_down_sync(0xffffffffu, v0, off);
            v1 += __shfl_down_sync(0xffffffffu, v1, off);
        }
        if (lane == 0) { red0[warp] = v0; red1[warp] = v1; }
        __syncthreads();

        if (h < 32) {
            float s0 = red0[h];
            float s1 = red1[h];
#pragma unroll
            for (int off = 16; off > 0; off >>= 1) {
                s0 += __shfl_down_sync(0xffffffffu, s0, off);
                s1 += __shfl_down_sync(0xffffffffu, s1, off);
            }
            if (h == 0) {
                float c0 = s0 + b20;
                float c1 = s1 + b21;
                float r2a = (mem2a > 1.0f) ? 1.0f : 0.0f;
                float r2b = (mem2b > 1.0f) ? 1.0f : 0.0f;
                syn2a = fmaf(ALPHA, syn2a, c0);
                syn2b = fmaf(ALPHA, syn2b, c1);
                mem2a = fmaf(BETA, mem2a, syn2a) - r2a;
                mem2b = fmaf(BETA, mem2b, syn2b) - r2b;
                size_t o = ((size_t)b * SNN_T + t) * 2;
                out_mem[o]     = mem2a;
                out_mem[o + 1] = mem2b;
                out_spk[o]     = (mem2a > 1.0f) ? 1.0f : 0.0f;
                out_spk[o + 1] = (mem2b > 1.0f) ? 1.0f : 0.0f;
            }
        }
        __syncthreads();   // protect red0/red1 before next step's writes
    }
}

// ---------------------------------------------------------------------------
// Launch
// ---------------------------------------------------------------------------
extern "C" void kernel_launch(void* const* d_in, const int* in_sizes, int n_in,
                              void* d_out, int out_size)
{
    const float* x  = (const float*)d_in[0];  // [B, T, 64, 64]
    const float* w1 = (const float*)d_in[1];  // [1024, 4096]
    const float* b1 = (const float*)d_in[2];  // [1024]
    const float* w2 = (const float*)d_in[3];  // [2, 1024]
    const float* b2 = (const float*)d_in[4];  // [2]
    float* out = (float*)d_out;               // [mem2: B*T*2][spk2: B*T*2]

    float* out_mem = out;
    float* out_spk = out + (size_t)SNN_B * SNN_T * SNN_NO;

    dim3 ggrid(SNN_NH / 128, SNN_M / 128);    // (8, 200)
    fc1_gemm<<<ggrid, 256>>>(x, w1, b1);
    snn_scan<<<SNN_B, 1024>>>(w2, b2, out_mem, out_spk);
    (void)in_sizes; (void)n_in; (void)out_size;
}